// round 11
// baseline (speedup 1.0000x reference)
#include <cuda_runtime.h>
#include <cuda_fp16.h>
#include <cstdint>

#define B_DIM 16
#define L_DIM 2048
#define F_DIM 512

#define CTA_M 128
#define CTA_N 128
#define KC    32
#define NCH   (L_DIM / KC)   /* 64 */
#define NSTAGE 4
#define THREADS 128

#define WSCALE 1024.0f
#define INV_WSCALE (1.0f / 1024.0f)

#define NGROUP 4
#define BPG    (B_DIM / NGROUP)

__device__ __half g_expw[(size_t)B_DIM * L_DIM * L_DIM];   /* 128 MB */
__device__ __half g_featx[(size_t)B_DIM * L_DIM * F_DIM];  /*  32 MB */

#define A_STAGE 8192
#define B_STAGE 8192
#define STAGE_BYTES (A_STAGE + B_STAGE)
#define SMEM_BYTES (NSTAGE * STAGE_BYTES)   /* 65536 per CTA, 2 CTAs/SM */

#define SM_ROWS_G (BPG * L_DIM)
#define FT_BLKS_G ((BPG * L_DIM * F_DIM) / (256 * 4))
#define FT4_PER_BATCH (L_DIM * F_DIM / 4)

/* ============== fused prepass (one batch group) ============== */
__global__ void __launch_bounds__(256, 8)
prep_fused(const float* __restrict__ noise, const float* __restrict__ feat, int bofs)
{
    const int tid = threadIdx.x;

    if (blockIdx.x >= SM_ROWS_G) {
        const size_t i = (size_t)bofs * FT4_PER_BATCH
                       + (size_t)(blockIdx.x - SM_ROWS_G) * 256 + tid;
        const float4 v = ((const float4*)feat)[i];
        __half2 p0 = __floats2half2_rn(v.x, v.y);
        __half2 p1 = __floats2half2_rn(v.z, v.w);
        uint2 u;
        u.x = *(uint32_t*)&p0; u.y = *(uint32_t*)&p1;
        ((uint2*)g_featx)[i] = u;
        return;
    }

    __shared__ float red[8];
    const int lane = tid & 31;
    const int w    = tid >> 5;
    const size_t r = (size_t)bofs * L_DIM + blockIdx.x;

    const float4* src = (const float4*)(noise + r * L_DIM);
    const float4 v0 = src[tid];
    const float4 v1 = src[tid + 256];

    float e0 = __expf(v0.x), e1 = __expf(v0.y), e2 = __expf(v0.z), e3 = __expf(v0.w);
    float e4 = __expf(v1.x), e5 = __expf(v1.y), e6 = __expf(v1.z), e7 = __expf(v1.w);

    float s = ((e0 + e1) + (e2 + e3)) + ((e4 + e5) + (e6 + e7));
    #pragma unroll
    for (int o = 16; o; o >>= 1) s += __shfl_xor_sync(0xFFFFFFFFu, s, o);
    if (lane == 0) red[w] = s;
    __syncthreads();
    if (tid == 0) {
        float t = 0.f;
        #pragma unroll
        for (int i = 0; i < 8; ++i) t += red[i];
        red[0] = WSCALE / t;
    }
    __syncthreads();
    const float inv = red[0];

    uint2* dst = (uint2*)(g_expw + r * L_DIM);
    __half2 p0 = __floats2half2_rn(e0 * inv, e1 * inv);
    __half2 p1 = __floats2half2_rn(e2 * inv, e3 * inv);
    __half2 p2 = __floats2half2_rn(e4 * inv, e5 * inv);
    __half2 p3 = __floats2half2_rn(e6 * inv, e7 * inv);
    uint2 u0, u1;
    u0.x = *(uint32_t*)&p0; u0.y = *(uint32_t*)&p1;
    u1.x = *(uint32_t*)&p2; u1.y = *(uint32_t*)&p3;
    dst[tid]       = u0;
    dst[tid + 256] = u1;
}

/* ============== main fp16 GEMM: s-granular fragment pipeline ============== */
__device__ __forceinline__ void mma_f16(float* c, const uint32_t* a, const uint32_t* b) {
    asm volatile(
        "mma.sync.aligned.m16n8k16.row.col.f32.f16.f16.f32 "
        "{%0,%1,%2,%3}, {%4,%5,%6,%7}, {%8,%9}, {%0,%1,%2,%3};"
        : "+f"(c[0]), "+f"(c[1]), "+f"(c[2]), "+f"(c[3])
        : "r"(a[0]), "r"(a[1]), "r"(a[2]), "r"(a[3]), "r"(b[0]), "r"(b[1]));
}

#define LDSM4(R, ADDR)                                                        \
    asm volatile("ldmatrix.sync.aligned.m8n8.x4.shared.b16 {%0,%1,%2,%3},[%4];" \
                 : "=r"((R)[0]), "=r"((R)[1]), "=r"((R)[2]), "=r"((R)[3]) : "r"(ADDR))

#define LDSM4T(R0, R1, R2, R3, ADDR)                                          \
    asm volatile("ldmatrix.sync.aligned.m8n8.x4.trans.shared.b16 {%0,%1,%2,%3},[%4];" \
                 : "=r"(R0), "=r"(R1), "=r"(R2), "=r"(R3) : "r"(ADDR))

#define CPA16(SADDR, GPTR)                                                    \
    asm volatile("cp.async.cg.shared.global [%0], [%1], 16;"                  \
                 :: "r"(SADDR), "l"(GPTR))

__global__ void __launch_bounds__(THREADS, 2)
FrameAugment_39771397161402_kernel(float* __restrict__ out, int bofs)
{
    extern __shared__ char smraw[];
    uint32_t sbase;
    asm("{ .reg .u64 t; cvta.to.shared.u64 t, %1; cvt.u32.u64 %0, t; }"
        : "=r"(sbase) : "l"(smraw));

    const int tid  = threadIdx.x;
    const int lane = tid & 31;
    const int w    = tid >> 5;
    const int q    = lane >> 2;
    const int qt   = lane & 3;
    const int wm   = w >> 1;
    const int wn   = w & 1;

    const int b  = blockIdx.z + bofs;
    const int m0 = blockIdx.x * CTA_M;
    const int n0 = blockIdx.y * CTA_N;

    const __half* aG = g_expw + ((size_t)b * L_DIM + m0) * L_DIM;
    const __half* bG = g_featx + (size_t)b * L_DIM * F_DIM + n0;
    float*        oG = out + ((size_t)b * L_DIM + m0) * F_DIM + n0;

    const int arow = tid >> 2, ac = tid & 3;
    const uint32_t aoff = (uint32_t)arow * 64u + (uint32_t)((ac ^ ((arow >> 1) & 3)) << 4);
    const size_t   gaoff = (size_t)arow * L_DIM + ac * 8;

    const int brow = tid >> 4, bc = tid & 15;
    const uint32_t boff = (uint32_t)brow * 256u +
                          (uint32_t)(((bc & 8) | ((bc & 7) ^ (brow & 7))) << 4);
    const size_t   gboff = (size_t)brow * F_DIM + bc * 8;

    const int l4   = lane >> 4;
    const int lk   = lane & 7;
    const int arw0 = wm * 64 + ((lane >> 3) & 1) * 8 + lk;
    const int akey = (arw0 >> 1) & 3;
    const int bk0  = ((lane >> 3) & 1) * 8 + lk;

#define LOAD_STAGE(IT, SLOT)                                                   \
    {                                                                          \
        const uint32_t sa = sbase + (SLOT) * STAGE_BYTES + aoff;               \
        const __half* ga = aG + (size_t)(IT) * KC + gaoff;                     \
        CPA16(sa,          ga);                                                \
        CPA16(sa + 2048u,  ga + (size_t)32 * L_DIM);                           \
        CPA16(sa + 4096u,  ga + (size_t)64 * L_DIM);                           \
        CPA16(sa + 6144u,  ga + (size_t)96 * L_DIM);                           \
        const uint32_t sb = sbase + (SLOT) * STAGE_BYTES + A_STAGE + boff;     \
        const __half* gb = bG + (size_t)(IT) * KC * F_DIM + gboff;             \
        CPA16(sb,          gb);                                                \
        CPA16(sb + 2048u,  gb + 8 * F_DIM);                                    \
        CPA16(sb + 4096u,  gb + 16 * F_DIM);                                   \
        CPA16(sb + 6144u,  gb + 24 * F_DIM);                                   \
        asm volatile("cp.async.commit_group;");                                \
    }

/* load one half-chunk (S in {0,1}) of fragments from stage SLOT */
#define LOAD_FRAG(FA, FB, SLOT, S)                                             \
    {                                                                          \
        const uint32_t Ab_ = sbase + (SLOT) * STAGE_BYTES;                     \
        const uint32_t Bb_ = Ab_ + A_STAGE;                                    \
        _Pragma("unroll")                                                      \
        for (int f = 0; f < 4; ++f) {                                          \
            const uint32_t addr = Ab_ + (uint32_t)(arw0 + 16 * f) * 64u        \
                                + (uint32_t)((((S) * 2 + l4) ^ akey) << 4);    \
            LDSM4((FA)[f], addr);                                              \
        }                                                                      \
        _Pragma("unroll")                                                      \
        for (int j = 0; j < 4; ++j) {                                          \
            const int cidx = wn * 8 + j * 2 + l4;                              \
            const uint32_t addr = Bb_ + (uint32_t)((S) * 16 + bk0) * 256u      \
                                + (uint32_t)(((cidx & 8) | ((cidx & 7) ^ lk)) << 4); \
            uint32_t t0, t1, t2, t3;                                           \
            LDSM4T(t0, t1, t2, t3, addr);                                      \
            (FB)[2 * j][0] = t0;     (FB)[2 * j][1] = t1;                      \
            (FB)[2 * j + 1][0] = t2; (FB)[2 * j + 1][1] = t3;                  \
        }                                                                      \
    }

#define MMA_ALL(FA, FB)                                                        \
    {                                                                          \
        _Pragma("unroll")                                                      \
        for (int f = 0; f < 4; ++f)                                            \
            _Pragma("unroll")                                                  \
            for (int g = 0; g < 8; ++g)                                        \
                mma_f16(c[f][g], (FA)[f], (FB)[g]);                            \
    }

    float c[4][8][4];
    #pragma unroll
    for (int f = 0; f < 4; ++f)
        #pragma unroll
        for (int g = 0; g < 8; ++g)
            #pragma unroll
            for (int k = 0; k < 4; ++k) c[f][g][k] = 0.f;

    uint32_t fa0[4][4], fb0[8][2];
    uint32_t fa1[4][4], fb1[8][2];

    LOAD_STAGE(0, 0);
    LOAD_STAGE(1, 1);
    LOAD_STAGE(2, 2);

    asm volatile("cp.async.wait_group %0;" :: "n"(NSTAGE - 2));
    __syncthreads();
    LOAD_FRAG(fa0, fb0, 0, 0);

    #pragma unroll 2
    for (int it = 0; it < NCH; ++it) {
        const int slot = it & (NSTAGE - 1);

        /* s0 phase: fetch s1 fragments, then MMA on s0 */
        LOAD_FRAG(fa1, fb1, slot, 1);
        MMA_ALL(fa0, fb0);

        /* s1 phase: advance pipeline to chunk it+1, then MMA on s1 */
        if (it + 1 < NCH) {
            if (it + NSTAGE - 1 < NCH) {
                LOAD_STAGE(it + NSTAGE - 1, (it + NSTAGE - 1) & (NSTAGE - 1));
            } else {
                asm volatile("cp.async.commit_group;");
            }
            asm volatile("cp.async.wait_group %0;" :: "n"(NSTAGE - 2));
            __syncthreads();
            LOAD_FRAG(fa0, fb0, (it + 1) & (NSTAGE - 1), 0);
        }
        MMA_ALL(fa1, fb1);
    }

    #pragma unroll
    for (int f = 0; f < 4; ++f) {
        const int r0 = wm * 64 + f * 16 + q;
        const int r1 = r0 + 8;
        #pragma unroll
        for (int g = 0; g < 8; ++g) {
            const int col = wn * 64 + g * 8 + 2 * qt;
            float2 lo, hi;
            lo.x = c[f][g][0] * INV_WSCALE;
            lo.y = c[f][g][1] * INV_WSCALE;
            hi.x = c[f][g][2] * INV_WSCALE;
            hi.y = c[f][g][3] * INV_WSCALE;
            __stcs((float2*)(oG + (size_t)r0 * F_DIM + col), lo);
            __stcs((float2*)(oG + (size_t)r1 * F_DIM + col), hi);
        }
    }
}

/* ============== host: forked-stream pipelined launch ============== */
static cudaStream_t sP, sG;
static cudaEvent_t  evRoot, evPrep[NGROUP], evEnd;

extern "C" void kernel_launch(void* const* d_in, const int* in_sizes, int n_in,
                              void* d_out, int out_size) {
    (void)in_sizes; (void)n_in; (void)out_size;
    const float* feature = (const float*)d_in[0];
    const float* noise   = (const float*)d_in[1];
    float* out = (float*)d_out;

    static const bool _init = []() {
        cudaStreamCreateWithFlags(&sP, cudaStreamNonBlocking);
        cudaStreamCreateWithFlags(&sG, cudaStreamNonBlocking);
        cudaEventCreateWithFlags(&evRoot, cudaEventDisableTiming);
        for (int g = 0; g < NGROUP; ++g)
            cudaEventCreateWithFlags(&evPrep[g], cudaEventDisableTiming);
        cudaEventCreateWithFlags(&evEnd, cudaEventDisableTiming);
        cudaFuncSetAttribute(FrameAugment_39771397161402_kernel,
                             cudaFuncAttributeMaxDynamicSharedMemorySize, SMEM_BYTES);
        return true;
    }();
    (void)_init;

    cudaEventRecord(evRoot, 0);
    cudaStreamWaitEvent(sP, evRoot, 0);
    cudaStreamWaitEvent(sG, evRoot, 0);

    for (int g = 0; g < NGROUP; ++g) {
        prep_fused<<<SM_ROWS_G + FT_BLKS_G, 256, 0, sP>>>(noise, feature, g * BPG);
        cudaEventRecord(evPrep[g], sP);
    }

    dim3 grid(L_DIM / CTA_M, F_DIM / CTA_N, BPG);   /* 16 x 4 x 4 = 256 CTAs */
    for (int g = 0; g < NGROUP; ++g) {
        cudaStreamWaitEvent(sG, evPrep[g], 0);
        FrameAugment_39771397161402_kernel<<<grid, THREADS, SMEM_BYTES, sG>>>(out, g * BPG);
    }

    cudaEventRecord(evEnd, sG);
    cudaStreamWaitEvent(0, evEnd, 0);
}

// round 13
// speedup vs baseline: 1.0725x; 1.0725x over previous
#include <cuda_runtime.h>
#include <cuda_fp16.h>
#include <cstdint>

#define B_DIM 16
#define L_DIM 2048
#define F_DIM 512

#define CTA_M 128
#define CTA_N 128
#define KC    32
#define NCH   (L_DIM / KC)   /* 64 */
#define NSTAGE 4
#define THREADS 128

#define WSCALE 1024.0f
#define INV_WSCALE (1.0f / 1024.0f)

#define NGROUP 4
#define BPG    (B_DIM / NGROUP)

__device__ __half g_expw[(size_t)B_DIM * L_DIM * L_DIM];   /* 128 MB */
__device__ __half g_featx[(size_t)B_DIM * L_DIM * F_DIM];  /*  32 MB */

#define A_STAGE 8192
#define B_STAGE 8192
#define STAGE_BYTES (A_STAGE + B_STAGE)
#define SMEM_BYTES (NSTAGE * STAGE_BYTES)   /* 65536 per CTA, 2 CTAs/SM */

#define SM_ROWS_G (BPG * L_DIM)
#define FT_BLKS_G ((BPG * L_DIM * F_DIM) / (256 * 4))
#define FT4_PER_BATCH (L_DIM * F_DIM / 4)

/* ============== fused prepass (one batch group) ============== */
__global__ void __launch_bounds__(256, 8)
prep_fused(const float* __restrict__ noise, const float* __restrict__ feat, int bofs)
{
    const int tid = threadIdx.x;

    if (blockIdx.x >= SM_ROWS_G) {
        const size_t i = (size_t)bofs * FT4_PER_BATCH
                       + (size_t)(blockIdx.x - SM_ROWS_G) * 256 + tid;
        const float4 v = __ldcs(((const float4*)feat) + i);
        __half2 p0 = __floats2half2_rn(v.x, v.y);
        __half2 p1 = __floats2half2_rn(v.z, v.w);
        uint2 u;
        u.x = *(uint32_t*)&p0; u.y = *(uint32_t*)&p1;
        ((uint2*)g_featx)[i] = u;
        return;
    }

    __shared__ float red[8];
    const int lane = tid & 31;
    const int w    = tid >> 5;
    const size_t r = (size_t)bofs * L_DIM + blockIdx.x;

    const float4* src = (const float4*)(noise + r * L_DIM);
    const float4 v0 = __ldcs(src + tid);
    const float4 v1 = __ldcs(src + tid + 256);

    float e0 = __expf(v0.x), e1 = __expf(v0.y), e2 = __expf(v0.z), e3 = __expf(v0.w);
    float e4 = __expf(v1.x), e5 = __expf(v1.y), e6 = __expf(v1.z), e7 = __expf(v1.w);

    float s = ((e0 + e1) + (e2 + e3)) + ((e4 + e5) + (e6 + e7));
    #pragma unroll
    for (int o = 16; o; o >>= 1) s += __shfl_xor_sync(0xFFFFFFFFu, s, o);
    if (lane == 0) red[w] = s;
    __syncthreads();
    if (tid == 0) {
        float t = 0.f;
        #pragma unroll
        for (int i = 0; i < 8; ++i) t += red[i];
        red[0] = WSCALE / t;
    }
    __syncthreads();
    const float inv = red[0];

    uint2* dst = (uint2*)(g_expw + r * L_DIM);
    __half2 p0 = __floats2half2_rn(e0 * inv, e1 * inv);
    __half2 p1 = __floats2half2_rn(e2 * inv, e3 * inv);
    __half2 p2 = __floats2half2_rn(e4 * inv, e5 * inv);
    __half2 p3 = __floats2half2_rn(e6 * inv, e7 * inv);
    uint2 u0, u1;
    u0.x = *(uint32_t*)&p0; u0.y = *(uint32_t*)&p1;
    u1.x = *(uint32_t*)&p2; u1.y = *(uint32_t*)&p3;
    dst[tid]       = u0;
    dst[tid + 256] = u1;
}

/* ============== main fp16 GEMM: R9 structure (verified best) ============== */
__device__ __forceinline__ void mma_f16(float* c, const uint32_t* a, const uint32_t* b) {
    asm volatile(
        "mma.sync.aligned.m16n8k16.row.col.f32.f16.f16.f32 "
        "{%0,%1,%2,%3}, {%4,%5,%6,%7}, {%8,%9}, {%0,%1,%2,%3};"
        : "+f"(c[0]), "+f"(c[1]), "+f"(c[2]), "+f"(c[3])
        : "r"(a[0]), "r"(a[1]), "r"(a[2]), "r"(a[3]), "r"(b[0]), "r"(b[1]));
}

#define LDSM4(R, ADDR)                                                        \
    asm volatile("ldmatrix.sync.aligned.m8n8.x4.shared.b16 {%0,%1,%2,%3},[%4];" \
                 : "=r"((R)[0]), "=r"((R)[1]), "=r"((R)[2]), "=r"((R)[3]) : "r"(ADDR))

#define LDSM4T(R0, R1, R2, R3, ADDR)                                          \
    asm volatile("ldmatrix.sync.aligned.m8n8.x4.trans.shared.b16 {%0,%1,%2,%3},[%4];" \
                 : "=r"(R0), "=r"(R1), "=r"(R2), "=r"(R3) : "r"(ADDR))

#define CPA16(SADDR, GPTR)                                                    \
    asm volatile("cp.async.cg.shared.global [%0], [%1], 16;"                  \
                 :: "r"(SADDR), "l"(GPTR))

__global__ void __launch_bounds__(THREADS, 2)
FrameAugment_39771397161402_kernel(float* __restrict__ out, int bofs)
{
    extern __shared__ char smraw[];
    uint32_t sbase;
    asm("{ .reg .u64 t; cvta.to.shared.u64 t, %1; cvt.u32.u64 %0, t; }"
        : "=r"(sbase) : "l"(smraw));

    const int tid  = threadIdx.x;
    const int lane = tid & 31;
    const int w    = tid >> 5;
    const int q    = lane >> 2;
    const int qt   = lane & 3;
    const int wm   = w >> 1;
    const int wn   = w & 1;

    const int b  = blockIdx.z + bofs;
    const int m0 = blockIdx.x * CTA_M;
    const int n0 = blockIdx.y * CTA_N;

    const __half* aG = g_expw + ((size_t)b * L_DIM + m0) * L_DIM;
    const __half* bG = g_featx + (size_t)b * L_DIM * F_DIM + n0;
    float*        oG = out + ((size_t)b * L_DIM + m0) * F_DIM + n0;

    const int arow = tid >> 2, ac = tid & 3;
    const uint32_t aoff = (uint32_t)arow * 64u + (uint32_t)((ac ^ ((arow >> 1) & 3)) << 4);
    const size_t   gaoff = (size_t)arow * L_DIM + ac * 8;

    const int brow = tid >> 4, bc = tid & 15;
    const uint32_t boff = (uint32_t)brow * 256u +
                          (uint32_t)(((bc & 8) | ((bc & 7) ^ (brow & 7))) << 4);
    const size_t   gboff = (size_t)brow * F_DIM + bc * 8;

    const int l4   = lane >> 4;
    const int lk   = lane & 7;
    const int arw0 = wm * 64 + ((lane >> 3) & 1) * 8 + lk;
    const int akey = (arw0 >> 1) & 3;
    const int bk0  = ((lane >> 3) & 1) * 8 + lk;

#define LOAD_STAGE(IT, SLOT)                                                   \
    {                                                                          \
        const uint32_t sa = sbase + (SLOT) * STAGE_BYTES + aoff;               \
        const __half* ga = aG + (size_t)(IT) * KC + gaoff;                     \
        CPA16(sa,          ga);                                                \
        CPA16(sa + 2048u,  ga + (size_t)32 * L_DIM);                           \
        CPA16(sa + 4096u,  ga + (size_t)64 * L_DIM);                           \
        CPA16(sa + 6144u,  ga + (size_t)96 * L_DIM);                           \
        const uint32_t sb = sbase + (SLOT) * STAGE_BYTES + A_STAGE + boff;     \
        const __half* gb = bG + (size_t)(IT) * KC * F_DIM + gboff;             \
        CPA16(sb,          gb);                                                \
        CPA16(sb + 2048u,  gb + 8 * F_DIM);                                    \
        CPA16(sb + 4096u,  gb + 16 * F_DIM);                                   \
        CPA16(sb + 6144u,  gb + 24 * F_DIM);                                   \
        asm volatile("cp.async.commit_group;");                                \
    }

    float c[4][8][4];
    #pragma unroll
    for (int f = 0; f < 4; ++f)
        #pragma unroll
        for (int g = 0; g < 8; ++g)
            #pragma unroll
            for (int k = 0; k < 4; ++k) c[f][g][k] = 0.f;

    LOAD_STAGE(0, 0);
    LOAD_STAGE(1, 1);
    LOAD_STAGE(2, 2);

    #pragma unroll 4
    for (int it = 0; it < NCH; ++it) {
        const int slot = it & (NSTAGE - 1);

        asm volatile("cp.async.wait_group %0;" :: "n"(NSTAGE - 2));
        __syncthreads();

        if (it + NSTAGE - 1 < NCH) {
            LOAD_STAGE(it + NSTAGE - 1, (it + NSTAGE - 1) & (NSTAGE - 1));
        } else {
            asm volatile("cp.async.commit_group;");
        }

        const uint32_t Ab = sbase + slot * STAGE_BYTES;
        const uint32_t Bb = Ab + A_STAGE;

        uint32_t a[2][4][4];
        uint32_t bb[2][8][2];
        #pragma unroll
        for (int s = 0; s < 2; ++s) {
            #pragma unroll
            for (int f = 0; f < 4; ++f) {
                const uint32_t addr = Ab + (uint32_t)(arw0 + 16 * f) * 64u
                                    + (uint32_t)(((s * 2 + l4) ^ akey) << 4);
                LDSM4(a[s][f], addr);
            }
            #pragma unroll
            for (int j = 0; j < 4; ++j) {
                const int cidx = wn * 8 + j * 2 + l4;
                const uint32_t addr = Bb + (uint32_t)(s * 16 + bk0) * 256u
                                    + (uint32_t)(((cidx & 8) | ((cidx & 7) ^ lk)) << 4);
                uint32_t t0, t1, t2, t3;
                LDSM4T(t0, t1, t2, t3, addr);
                bb[s][2 * j][0] = t0;     bb[s][2 * j][1] = t1;
                bb[s][2 * j + 1][0] = t2; bb[s][2 * j + 1][1] = t3;
            }
        }
        #pragma unroll
        for (int s = 0; s < 2; ++s)
            #pragma unroll
            for (int f = 0; f < 4; ++f)
                #pragma unroll
                for (int g = 0; g < 8; ++g)
                    mma_f16(c[f][g], a[s][f], bb[s][g]);
    }

    #pragma unroll
    for (int f = 0; f < 4; ++f) {
        const int r0 = wm * 64 + f * 16 + q;
        const int r1 = r0 + 8;
        #pragma unroll
        for (int g = 0; g < 8; ++g) {
            const int col = wn * 64 + g * 8 + 2 * qt;
            float2 lo, hi;
            lo.x = c[f][g][0] * INV_WSCALE;
            lo.y = c[f][g][1] * INV_WSCALE;
            hi.x = c[f][g][2] * INV_WSCALE;
            hi.y = c[f][g][3] * INV_WSCALE;
            __stcs((float2*)(oG + (size_t)r0 * F_DIM + col), lo);
            __stcs((float2*)(oG + (size_t)r1 * F_DIM + col), hi);
        }
    }
}

/* ============== host: 2 streams (R10 footprint), staggered GEMM groups ============== */
static cudaStream_t sP, sG;
static cudaEvent_t  evRoot, evPrep[3], evEndP, evEndG;

extern "C" void kernel_launch(void* const* d_in, const int* in_sizes, int n_in,
                              void* d_out, int out_size) {
    (void)in_sizes; (void)n_in; (void)out_size;
    const float* feature = (const float*)d_in[0];
    const float* noise   = (const float*)d_in[1];
    float* out = (float*)d_out;

    static const bool _init = []() {
        cudaStreamCreateWithFlags(&sP, cudaStreamNonBlocking);
        cudaStreamCreateWithFlags(&sG, cudaStreamNonBlocking);
        cudaEventCreateWithFlags(&evRoot, cudaEventDisableTiming);
        for (int g = 0; g < 3; ++g)
            cudaEventCreateWithFlags(&evPrep[g], cudaEventDisableTiming);
        cudaEventCreateWithFlags(&evEndP, cudaEventDisableTiming);
        cudaEventCreateWithFlags(&evEndG, cudaEventDisableTiming);
        cudaFuncSetAttribute(FrameAugment_39771397161402_kernel,
                             cudaFuncAttributeMaxDynamicSharedMemorySize, SMEM_BYTES);
        return true;
    }();
    (void)_init;

    /* fork both streams off the launch stream */
    cudaEventRecord(evRoot, 0);
    cudaStreamWaitEvent(sP, evRoot, 0);
    cudaStreamWaitEvent(sG, evRoot, 0);

    dim3 grid(L_DIM / CTA_M, F_DIM / CTA_N, BPG);   /* 16 x 4 x 4 = 256 CTAs */

    /* sP: all prep groups, then GEMM group 3 (ordered after prep3 implicitly) */
    for (int g = 0; g < NGROUP; ++g) {
        prep_fused<<<SM_ROWS_G + FT_BLKS_G, 256, 0, sP>>>(noise, feature, g * BPG);
        if (g < 3) cudaEventRecord(evPrep[g], sP);
    }
    FrameAugment_39771397161402_kernel<<<grid, THREADS, SMEM_BYTES, sP>>>(out, 3 * BPG);
    cudaEventRecord(evEndP, sP);

    /* sG: GEMM groups 0..2, each gated only on its own prep */
    for (int g = 0; g < 3; ++g) {
        cudaStreamWaitEvent(sG, evPrep[g], 0);
        FrameAugment_39771397161402_kernel<<<grid, THREADS, SMEM_BYTES, sG>>>(out, g * BPG);
    }
    cudaEventRecord(evEndG, sG);

    /* join */
    cudaStreamWaitEvent(0, evEndP, 0);
    cudaStreamWaitEvent(0, evEndG, 0);
}

// round 14
// speedup vs baseline: 1.0992x; 1.0249x over previous
#include <cuda_runtime.h>
#include <cuda_fp16.h>
#include <cstdint>

#define B_DIM 16
#define L_DIM 2048
#define F_DIM 512

#define CTA_M 128
#define CTA_N 128
#define KC    32
#define NCH   (L_DIM / KC)   /* 64 */
#define NSTAGE 6
#define THREADS 128

#define WSCALE 1024.0f
#define INV_WSCALE (1.0f / 1024.0f)

#define NGROUP 4
#define BPG    (B_DIM / NGROUP)

__device__ __half g_expw[(size_t)B_DIM * L_DIM * L_DIM];   /* 128 MB */
__device__ __half g_featx[(size_t)B_DIM * L_DIM * F_DIM];  /*  32 MB */

#define A_STAGE 8192
#define B_STAGE 8192
#define STAGE_BYTES (A_STAGE + B_STAGE)
#define SMEM_BYTES (NSTAGE * STAGE_BYTES)   /* 98304 per CTA, 2 CTAs/SM */

#define SM_ROWS_G (BPG * L_DIM)
#define FT_BLKS_G ((BPG * L_DIM * F_DIM) / (256 * 4))
#define FT4_PER_BATCH (L_DIM * F_DIM / 4)

/* ============== fused prepass (one batch group) ============== */
__global__ void __launch_bounds__(256, 8)
prep_fused(const float* __restrict__ noise, const float* __restrict__ feat, int bofs)
{
    const int tid = threadIdx.x;

    if (blockIdx.x >= SM_ROWS_G) {
        const size_t i = (size_t)bofs * FT4_PER_BATCH
                       + (size_t)(blockIdx.x - SM_ROWS_G) * 256 + tid;
        const float4 v = __ldcs(((const float4*)feat) + i);
        __half2 p0 = __floats2half2_rn(v.x, v.y);
        __half2 p1 = __floats2half2_rn(v.z, v.w);
        uint2 u;
        u.x = *(uint32_t*)&p0; u.y = *(uint32_t*)&p1;
        ((uint2*)g_featx)[i] = u;
        return;
    }

    __shared__ float red[8];
    const int lane = tid & 31;
    const int w    = tid >> 5;
    const size_t r = (size_t)bofs * L_DIM + blockIdx.x;

    const float4* src = (const float4*)(noise + r * L_DIM);
    const float4 v0 = __ldcs(src + tid);
    const float4 v1 = __ldcs(src + tid + 256);

    float e0 = __expf(v0.x), e1 = __expf(v0.y), e2 = __expf(v0.z), e3 = __expf(v0.w);
    float e4 = __expf(v1.x), e5 = __expf(v1.y), e6 = __expf(v1.z), e7 = __expf(v1.w);

    float s = ((e0 + e1) + (e2 + e3)) + ((e4 + e5) + (e6 + e7));
    #pragma unroll
    for (int o = 16; o; o >>= 1) s += __shfl_xor_sync(0xFFFFFFFFu, s, o);
    if (lane == 0) red[w] = s;
    __syncthreads();
    if (tid == 0) {
        float t = 0.f;
        #pragma unroll
        for (int i = 0; i < 8; ++i) t += red[i];
        red[0] = WSCALE / t;
    }
    __syncthreads();
    const float inv = red[0];

    uint2* dst = (uint2*)(g_expw + r * L_DIM);
    __half2 p0 = __floats2half2_rn(e0 * inv, e1 * inv);
    __half2 p1 = __floats2half2_rn(e2 * inv, e3 * inv);
    __half2 p2 = __floats2half2_rn(e4 * inv, e5 * inv);
    __half2 p3 = __floats2half2_rn(e6 * inv, e7 * inv);
    uint2 u0, u1;
    u0.x = *(uint32_t*)&p0; u0.y = *(uint32_t*)&p1;
    u1.x = *(uint32_t*)&p2; u1.y = *(uint32_t*)&p3;
    dst[tid]       = u0;
    dst[tid + 256] = u1;
}

/* ============== main fp16 GEMM: R9 inner loop, 6-stage ring ============== */
__device__ __forceinline__ void mma_f16(float* c, const uint32_t* a, const uint32_t* b) {
    asm volatile(
        "mma.sync.aligned.m16n8k16.row.col.f32.f16.f16.f32 "
        "{%0,%1,%2,%3}, {%4,%5,%6,%7}, {%8,%9}, {%0,%1,%2,%3};"
        : "+f"(c[0]), "+f"(c[1]), "+f"(c[2]), "+f"(c[3])
        : "r"(a[0]), "r"(a[1]), "r"(a[2]), "r"(a[3]), "r"(b[0]), "r"(b[1]));
}

#define LDSM4(R, ADDR)                                                        \
    asm volatile("ldmatrix.sync.aligned.m8n8.x4.shared.b16 {%0,%1,%2,%3},[%4];" \
                 : "=r"((R)[0]), "=r"((R)[1]), "=r"((R)[2]), "=r"((R)[3]) : "r"(ADDR))

#define LDSM4T(R0, R1, R2, R3, ADDR)                                          \
    asm volatile("ldmatrix.sync.aligned.m8n8.x4.trans.shared.b16 {%0,%1,%2,%3},[%4];" \
                 : "=r"(R0), "=r"(R1), "=r"(R2), "=r"(R3) : "r"(ADDR))

#define CPA16(SADDR, GPTR)                                                    \
    asm volatile("cp.async.cg.shared.global [%0], [%1], 16;"                  \
                 :: "r"(SADDR), "l"(GPTR))

__global__ void __launch_bounds__(THREADS, 2)
FrameAugment_39771397161402_kernel(float* __restrict__ out, int bofs)
{
    extern __shared__ char smraw[];
    uint32_t sbase;
    asm("{ .reg .u64 t; cvta.to.shared.u64 t, %1; cvt.u32.u64 %0, t; }"
        : "=r"(sbase) : "l"(smraw));

    const int tid  = threadIdx.x;
    const int lane = tid & 31;
    const int w    = tid >> 5;
    const int q    = lane >> 2;
    const int qt   = lane & 3;
    const int wm   = w >> 1;
    const int wn   = w & 1;

    const int b  = blockIdx.z + bofs;
    const int m0 = blockIdx.x * CTA_M;
    const int n0 = blockIdx.y * CTA_N;

    const __half* aG = g_expw + ((size_t)b * L_DIM + m0) * L_DIM;
    const __half* bG = g_featx + (size_t)b * L_DIM * F_DIM + n0;
    float*        oG = out + ((size_t)b * L_DIM + m0) * F_DIM + n0;

    const int arow = tid >> 2, ac = tid & 3;
    const uint32_t aoff = (uint32_t)arow * 64u + (uint32_t)((ac ^ ((arow >> 1) & 3)) << 4);
    const size_t   gaoff = (size_t)arow * L_DIM + ac * 8;

    const int brow = tid >> 4, bc = tid & 15;
    const uint32_t boff = (uint32_t)brow * 256u +
                          (uint32_t)(((bc & 8) | ((bc & 7) ^ (brow & 7))) << 4);
    const size_t   gboff = (size_t)brow * F_DIM + bc * 8;

    const int l4   = lane >> 4;
    const int lk   = lane & 7;
    const int arw0 = wm * 64 + ((lane >> 3) & 1) * 8 + lk;
    const int akey = (arw0 >> 1) & 3;
    const int bk0  = ((lane >> 3) & 1) * 8 + lk;

#define LOAD_STAGE(IT, SLOT)                                                   \
    {                                                                          \
        const uint32_t sa = sbase + (SLOT) * STAGE_BYTES + aoff;               \
        const __half* ga = aG + (size_t)(IT) * KC + gaoff;                     \
        CPA16(sa,          ga);                                                \
        CPA16(sa + 2048u,  ga + (size_t)32 * L_DIM);                           \
        CPA16(sa + 4096u,  ga + (size_t)64 * L_DIM);                           \
        CPA16(sa + 6144u,  ga + (size_t)96 * L_DIM);                           \
        const uint32_t sb = sbase + (SLOT) * STAGE_BYTES + A_STAGE + boff;     \
        const __half* gb = bG + (size_t)(IT) * KC * F_DIM + gboff;             \
        CPA16(sb,          gb);                                                \
        CPA16(sb + 2048u,  gb + 8 * F_DIM);                                    \
        CPA16(sb + 4096u,  gb + 16 * F_DIM);                                   \
        CPA16(sb + 6144u,  gb + 24 * F_DIM);                                   \
        asm volatile("cp.async.commit_group;");                                \
    }

    float c[4][8][4];
    #pragma unroll
    for (int f = 0; f < 4; ++f)
        #pragma unroll
        for (int g = 0; g < 8; ++g)
            #pragma unroll
            for (int k = 0; k < 4; ++k) c[f][g][k] = 0.f;

    LOAD_STAGE(0, 0);
    LOAD_STAGE(1, 1);
    LOAD_STAGE(2, 2);
    LOAD_STAGE(3, 3);
    LOAD_STAGE(4, 4);

    int slot = 0;           /* slot of chunk `it` */
    int nslot = 5;          /* slot for chunk `it + NSTAGE - 1` */
    for (int it = 0; it < NCH; ++it) {
        asm volatile("cp.async.wait_group %0;" :: "n"(NSTAGE - 2));
        __syncthreads();

        if (it + NSTAGE - 1 < NCH) {
            LOAD_STAGE(it + NSTAGE - 1, nslot);
        } else {
            asm volatile("cp.async.commit_group;");
        }

        const uint32_t Ab = sbase + slot * STAGE_BYTES;
        const uint32_t Bb = Ab + A_STAGE;

        uint32_t a[2][4][4];
        uint32_t bb[2][8][2];
        #pragma unroll
        for (int s = 0; s < 2; ++s) {
            #pragma unroll
            for (int f = 0; f < 4; ++f) {
                const uint32_t addr = Ab + (uint32_t)(arw0 + 16 * f) * 64u
                                    + (uint32_t)(((s * 2 + l4) ^ akey) << 4);
                LDSM4(a[s][f], addr);
            }
            #pragma unroll
            for (int j = 0; j < 4; ++j) {
                const int cidx = wn * 8 + j * 2 + l4;
                const uint32_t addr = Bb + (uint32_t)(s * 16 + bk0) * 256u
                                    + (uint32_t)(((cidx & 8) | ((cidx & 7) ^ lk)) << 4);
                uint32_t t0, t1, t2, t3;
                LDSM4T(t0, t1, t2, t3, addr);
                bb[s][2 * j][0] = t0;     bb[s][2 * j][1] = t1;
                bb[s][2 * j + 1][0] = t2; bb[s][2 * j + 1][1] = t3;
            }
        }
        #pragma unroll
        for (int s = 0; s < 2; ++s)
            #pragma unroll
            for (int f = 0; f < 4; ++f)
                #pragma unroll
                for (int g = 0; g < 8; ++g)
                    mma_f16(c[f][g], a[s][f], bb[s][g]);

        slot  = (slot == NSTAGE - 1) ? 0 : slot + 1;
        nslot = (nslot == NSTAGE - 1) ? 0 : nslot + 1;
    }

    #pragma unroll
    for (int f = 0; f < 4; ++f) {
        const int r0 = wm * 64 + f * 16 + q;
        const int r1 = r0 + 8;
        #pragma unroll
        for (int g = 0; g < 8; ++g) {
            const int col = wn * 64 + g * 8 + 2 * qt;
            float2 lo, hi;
            lo.x = c[f][g][0] * INV_WSCALE;
            lo.y = c[f][g][1] * INV_WSCALE;
            hi.x = c[f][g][2] * INV_WSCALE;
            hi.y = c[f][g][3] * INV_WSCALE;
            __stcs((float2*)(oG + (size_t)r0 * F_DIM + col), lo);
            __stcs((float2*)(oG + (size_t)r1 * F_DIM + col), hi);
        }
    }
}

/* ============== host: 2 streams (proven footprint), staggered GEMM groups ============== */
static cudaStream_t sP, sG;
static cudaEvent_t  evRoot, evPrep[3], evEndP, evEndG;

extern "C" void kernel_launch(void* const* d_in, const int* in_sizes, int n_in,
                              void* d_out, int out_size) {
    (void)in_sizes; (void)n_in; (void)out_size;
    const float* feature = (const float*)d_in[0];
    const float* noise   = (const float*)d_in[1];
    float* out = (float*)d_out;

    static const bool _init = []() {
        cudaStreamCreateWithFlags(&sP, cudaStreamNonBlocking);
        cudaStreamCreateWithFlags(&sG, cudaStreamNonBlocking);
        cudaEventCreateWithFlags(&evRoot, cudaEventDisableTiming);
        for (int g = 0; g < 3; ++g)
            cudaEventCreateWithFlags(&evPrep[g], cudaEventDisableTiming);
        cudaEventCreateWithFlags(&evEndP, cudaEventDisableTiming);
        cudaEventCreateWithFlags(&evEndG, cudaEventDisableTiming);
        cudaFuncSetAttribute(FrameAugment_39771397161402_kernel,
                             cudaFuncAttributeMaxDynamicSharedMemorySize, SMEM_BYTES);
        return true;
    }();
    (void)_init;

    cudaEventRecord(evRoot, 0);
    cudaStreamWaitEvent(sP, evRoot, 0);
    cudaStreamWaitEvent(sG, evRoot, 0);

    dim3 grid(L_DIM / CTA_M, F_DIM / CTA_N, BPG);   /* 16 x 4 x 4 = 256 CTAs */

    /* sP: all prep groups, then GEMM group 3 */
    for (int g = 0; g < NGROUP; ++g) {
        prep_fused<<<SM_ROWS_G + FT_BLKS_G, 256, 0, sP>>>(noise, feature, g * BPG);
        if (g < 3) cudaEventRecord(evPrep[g], sP);
    }
    FrameAugment_39771397161402_kernel<<<grid, THREADS, SMEM_BYTES, sP>>>(out, 3 * BPG);
    cudaEventRecord(evEndP, sP);

    /* sG: GEMM groups 0..2, each gated only on its own prep */
    for (int g = 0; g < 3; ++g) {
        cudaStreamWaitEvent(sG, evPrep[g], 0);
        FrameAugment_39771397161402_kernel<<<grid, THREADS, SMEM_BYTES, sG>>>(out, g * BPG);
    }
    cudaEventRecord(evEndG, sG);

    cudaStreamWaitEvent(0, evEndP, 0);
    cudaStreamWaitEvent(0, evEndG, 0);
}